// round 4
// baseline (speedup 1.0000x reference)
#include <cuda_runtime.h>
#include <math.h>

#define THREADS 512
#define TB 128
#define PX 68           // pitch (floats) for X/H/W smem rows

// smem layout (floats):
//   buf0: 128*68 = 8704
//   buf1: 128*68 = 8704
//   sB  : big region, 37808 floats (conv stage uses all of it; GRU uses 32704)
#define SMEM_FLOATS (8704 + 8704 + 37808)
#define SMEM_BYTES  (SMEM_FLOATS * 4)

#define SCR_PITCH 194   // scratch pitch for gh partials (degree-2 conflicts, epilogue only)

struct KParams {
    const float* in[32];
    float* out;
    int B;
};

__device__ __forceinline__ float sigmoidf_(float x) { return 1.0f / (1.0f + expf(-x)); }

__device__ __forceinline__ void load_h(float* __restrict__ sH, const float* __restrict__ gmem,
                                       int gs0, int off, int tid)
{
    for (int idx = tid; idx < TB * 64; idx += THREADS) {
        int s = idx >> 6, j = idx & 63;
        sH[s * PX + j] = gmem[(size_t)(gs0 + s) * 256 + off + j];
    }
}

// One GRU cell for TB samples, operand-split across two thread halves:
//   warps 0-7  (half=0): gi = x @ Wi^T   (keeps partials in regs)
//   warps 8-15 (half=1): gh = h @ Wh^T   (writes partials to smem scratch)
// Half A combines, applies gates, updates sH in place + writes memory_out.
__device__ __forceinline__ void gru_cell(
    const float* __restrict__ sX, float* __restrict__ sH, float* __restrict__ sB,
    const float* __restrict__ g_wih, const float* __restrict__ g_whh,
    const float* __restrict__ g_bih, const float* __restrict__ g_bhh,
    float* __restrict__ out_mem, int gs0, int cell_off, int tid)
{
    float* Wi  = sB;                    // 192*68 = 13056
    float* Wh  = sB + 192 * PX;         // 192*68
    float* bi  = sB + 2 * 192 * PX;     // 192
    float* bh  = bi + 192;              // 192
    float* scr = bh + 192;              // 32*SCR_PITCH = 6208

    for (int idx = tid; idx < 192 * 64; idx += THREADS) {
        int r = idx >> 6, c = idx & 63;
        Wi[r * PX + c] = g_wih[idx];
        Wh[r * PX + c] = g_whh[idx];
    }
    for (int idx = tid; idx < 192; idx += THREADS) { bi[idx] = g_bih[idx]; bh[idx] = g_bhh[idx]; }
    __syncthreads();

    const int half = tid >> 8;          // warp-uniform (warps 0-7 vs 8-15)
    const int t  = tid & 255;
    const int ts = t & 7;               // sample lane 0..7
    const int tj = t >> 3;              // j lane 0..31
    const float* src = half ? sH : sX;
    const float* W   = half ? Wh : Wi;

    for (int sub = 0; sub < 4; ++sub) {
        const int sb = sub * 32;
        float acc[4][2][3];
        #pragma unroll
        for (int u = 0; u < 4; u++)
            #pragma unroll
            for (int js = 0; js < 2; js++)
                #pragma unroll
                for (int g = 0; g < 3; g++) acc[u][js][g] = 0.f;

        #pragma unroll 2
        for (int k = 0; k < 64; k += 4) {
            float4 xv[4];
            #pragma unroll
            for (int u = 0; u < 4; u++)
                xv[u] = *reinterpret_cast<const float4*>(&src[(sb + ts + 8 * u) * PX + k]);
            float4 wv[2][3];
            #pragma unroll
            for (int js = 0; js < 2; js++) {
                int j = tj + 32 * js;
                wv[js][0] = *reinterpret_cast<const float4*>(&W[(j      ) * PX + k]);
                wv[js][1] = *reinterpret_cast<const float4*>(&W[(j + 64 ) * PX + k]);
                wv[js][2] = *reinterpret_cast<const float4*>(&W[(j + 128) * PX + k]);
            }
            #pragma unroll
            for (int u = 0; u < 4; u++)
                #pragma unroll
                for (int js = 0; js < 2; js++)
                    #pragma unroll
                    for (int g = 0; g < 3; g++) {
                        float4 a = xv[u];
                        float4 w = wv[js][g];
                        acc[u][js][g] += a.x * w.x + a.y * w.y + a.z * w.z + a.w * w.w;
                    }
        }

        if (half) {
            // publish gh partials: scr[local_sample][j + 64*g]
            #pragma unroll
            for (int u = 0; u < 4; u++) {
                int sl = ts + 8 * u;
                #pragma unroll
                for (int js = 0; js < 2; js++) {
                    int j = tj + 32 * js;
                    scr[sl * SCR_PITCH + j      ] = acc[u][js][0];
                    scr[sl * SCR_PITCH + j + 64 ] = acc[u][js][1];
                    scr[sl * SCR_PITCH + j + 128] = acc[u][js][2];
                }
            }
        }
        __syncthreads();   // gh visible; all k-loop reads of this subtile's sH rows done

        if (!half) {
            #pragma unroll
            for (int u = 0; u < 4; u++) {
                int sl = ts + 8 * u;
                int s  = sb + sl;
                int gs = gs0 + s;
                #pragma unroll
                for (int js = 0; js < 2; js++) {
                    int j = tj + 32 * js;
                    float hr = scr[sl * SCR_PITCH + j      ];
                    float hz = scr[sl * SCR_PITCH + j + 64 ];
                    float hn = scr[sl * SCR_PITCH + j + 128];
                    float r = sigmoidf_(acc[u][js][0] + hr + bi[j] + bh[j]);
                    float z = sigmoidf_(acc[u][js][1] + hz + bi[64 + j] + bh[64 + j]);
                    float n = tanhf(acc[u][js][2] + bi[128 + j] + r * (hn + bh[128 + j]));
                    float h = sH[s * PX + j];
                    float hnew = (1.f - z) * n + z * h;
                    sH[s * PX + j] = hnew;
                    out_mem[(size_t)gs * 256 + cell_off + j] = hnew;
                }
            }
        }
        __syncthreads();   // scratch free for next subtile
    }
}

__global__ __launch_bounds__(THREADS, 1)
void fused_gru_ac_kernel(KParams P)
{
    extern __shared__ float sm[];
    float* buf0 = sm;
    float* buf1 = sm + 8704;
    float* sB   = sm + 17408;

    const int tid = threadIdx.x;
    const int gs0 = blockIdx.x * TB;
    const int Btot = P.B;

    const float* g_obs = P.in[0];
    const float* g_mem = P.in[1];
    float* out_mem = P.out + (size_t)4 * Btot;   // memory_out region

    // ---------------- conv weights -> smem (once) ----------------
    {
        const float* g;
        g = P.in[2]; for (int i = tid; i < 192;  i += THREADS) sB[i]        = g[i];   // w1
        g = P.in[3]; for (int i = tid; i < 16;   i += THREADS) sB[192 + i]  = g[i];   // b1
        g = P.in[4]; for (int i = tid; i < 2048; i += THREADS) sB[208 + i]  = g[i];   // w2
        g = P.in[5]; for (int i = tid; i < 32;   i += THREADS) sB[2256 + i] = g[i];   // b2
        g = P.in[6]; for (int i = tid; i < 8192; i += THREADS) sB[2288 + i] = g[i];   // w3
        g = P.in[7]; for (int i = tid; i < 64;   i += THREADS) sB[10480 + i] = g[i];  // b3
    }
    float* obsS = sB + 10544;   // 64*149
    float* Pm   = sB + 20080;   // 64*145
    float* o2   = sB + 29360;   // 64*132

    // ---------------- conv stack: 2 passes of 64 samples, 8 threads/sample ----------------
    for (int pass = 0; pass < 2; ++pass) {
        int sg0 = gs0 + pass * 64;
        for (int idx = tid; idx < 64 * 147; idx += THREADS) {
            int s = idx / 147, e = idx - s * 147;
            obsS[s * 149 + e] = g_obs[(size_t)(sg0 + s) * 147 + e];
        }
        __syncthreads();

        int s = tid >> 3, q = tid & 7;   // 8 threads per sample (channel splits)

        // conv1 (3->16, 2x2) + relu + maxpool2 -> Pm[16][3][3]   (2 out ch / thread)
        {
            float w1r[24], b1r[2];
            #pragma unroll
            for (int oc = 0; oc < 2; oc++) {
                int o = q * 2 + oc;
                #pragma unroll
                for (int m = 0; m < 12; m++) w1r[oc * 12 + m] = sB[o * 12 + m];
                b1r[oc] = sB[192 + o];
            }
            for (int i = 0; i < 3; i++)
                for (int j = 0; j < 3; j++) {
                    float xv[27];
                    #pragma unroll
                    for (int c = 0; c < 3; c++)
                        #pragma unroll
                        for (int a = 0; a < 3; a++)
                            #pragma unroll
                            for (int b = 0; b < 3; b++)
                                xv[c * 9 + a * 3 + b] =
                                    obsS[s * 149 + (2 * i + a) * 21 + (2 * j + b) * 3 + c];
                    #pragma unroll
                    for (int oc = 0; oc < 2; oc++) {
                        float mx = -1e30f;
                        #pragma unroll
                        for (int pi = 0; pi < 2; pi++)
                            #pragma unroll
                            for (int pj = 0; pj < 2; pj++) {
                                float a0 = b1r[oc];
                                #pragma unroll
                                for (int c = 0; c < 3; c++)
                                    #pragma unroll
                                    for (int ki = 0; ki < 2; ki++)
                                        #pragma unroll
                                        for (int kj = 0; kj < 2; kj++)
                                            a0 += xv[c * 9 + (pi + ki) * 3 + (pj + kj)] *
                                                  w1r[oc * 12 + c * 4 + ki * 2 + kj];
                                a0 = fmaxf(a0, 0.f);
                                mx = fmaxf(mx, a0);
                            }
                        Pm[s * 145 + (q * 2 + oc) * 9 + i * 3 + j] = mx;
                    }
                }
        }
        __syncthreads();

        // conv2 (16->32, 2x2 on 3x3) + relu -> o2[32][2][2]   (4 out ch / thread)
        #pragma unroll
        for (int pi = 0; pi < 2; pi++)
            #pragma unroll
            for (int pj = 0; pj < 2; pj++) {
                float xp[64];
                #pragma unroll
                for (int c = 0; c < 16; c++)
                    #pragma unroll
                    for (int a = 0; a < 2; a++)
                        #pragma unroll
                        for (int b = 0; b < 2; b++)
                            xp[c * 4 + a * 2 + b] = Pm[s * 145 + c * 9 + (pi + a) * 3 + (pj + b)];
                for (int o4 = 0; o4 < 4; o4++) {
                    int o = q * 4 + o4;
                    float a0 = sB[2256 + o];
                    #pragma unroll
                    for (int kk = 0; kk < 16; kk++) {
                        float4 w = *reinterpret_cast<const float4*>(&sB[208 + o * 64 + kk * 4]);
                        a0 += xp[kk * 4] * w.x + xp[kk * 4 + 1] * w.y +
                              xp[kk * 4 + 2] * w.z + xp[kk * 4 + 3] * w.w;
                    }
                    o2[s * 132 + o * 4 + pi * 2 + pj] = fmaxf(a0, 0.f);
                }
            }
        __syncthreads();

        // conv3 (32->64, 2x2 on 2x2) + relu -> x[64] into buf0   (8 out ch / thread)
        for (int o8 = 0; o8 < 8; o8++) {
            int o = q * 8 + o8;
            float a0 = sB[10480 + o];
            #pragma unroll
            for (int kk = 0; kk < 32; kk++) {
                float4 w  = *reinterpret_cast<const float4*>(&sB[2288 + o * 128 + kk * 4]);
                float4 x4 = *reinterpret_cast<const float4*>(&o2[s * 132 + kk * 4]);
                a0 += x4.x * w.x + x4.y * w.y + x4.z * w.z + x4.w * w.w;
            }
            buf0[(pass * 64 + s) * PX + o] = fmaxf(a0, 0.f);
        }
        __syncthreads();
    }

    // ---------------- 4 GRU cells ----------------
    float* Xp = buf0;
    float* Hp = buf1;

    load_h(Hp, g_mem, gs0, 0, tid);
    gru_cell(Xp, Hp, sB, P.in[8],  P.in[9],  P.in[10], P.in[11], out_mem, gs0, 0,   tid);
    { float* t = Xp; Xp = Hp; Hp = t; }

    load_h(Hp, g_mem, gs0, 64, tid);
    gru_cell(Xp, Hp, sB, P.in[12], P.in[13], P.in[14], P.in[15], out_mem, gs0, 64,  tid);
    { float* t = Xp; Xp = Hp; Hp = t; }

    load_h(Hp, g_mem, gs0, 128, tid);
    gru_cell(Xp, Hp, sB, P.in[16], P.in[17], P.in[18], P.in[19], out_mem, gs0, 128, tid);
    { float* t = Xp; Xp = Hp; Hp = t; }

    load_h(Hp, g_mem, gs0, 192, tid);
    gru_cell(Xp, Hp, sB, P.in[20], P.in[21], P.in[22], P.in[23], out_mem, gs0, 192, tid);
    { float* t = Xp; Xp = Hp; Hp = t; }
    // Xp = embedding [TB][PX], Hp = scratch

    // ---------------- heads ----------------
    float* HW  = sB;            // 128 rows x PX: rows 0..63 actor_w1, 64..127 critic_w1
    float* ab1 = sB + 8704;     // 64
    float* cb1 = sB + 8768;     // 64
    float* aw2 = sB + 8832;     // 3*64
    float* ab2 = sB + 9024;     // 3
    float* cw2 = sB + 9027;     // 64
    float* cb2 = sB + 9091;     // 1
    float* C1  = sB + 9092;     // 128 x PX

    {
        const float* ga = P.in[24];  // actor_w1 [64][64]
        const float* gc = P.in[28];  // critic_w1 [64][64]
        for (int idx = tid; idx < 64 * 64; idx += THREADS) {
            int r = idx >> 6, c = idx & 63;
            HW[r * PX + c]        = ga[idx];
            HW[(64 + r) * PX + c] = gc[idx];
        }
        const float* g;
        g = P.in[25]; for (int i = tid; i < 64;  i += THREADS) ab1[i] = g[i];
        g = P.in[29]; for (int i = tid; i < 64;  i += THREADS) cb1[i] = g[i];
        g = P.in[26]; for (int i = tid; i < 192; i += THREADS) aw2[i] = g[i];
        g = P.in[27]; for (int i = tid; i < 3;   i += THREADS) ab2[i] = g[i];
        g = P.in[30]; for (int i = tid; i < 64;  i += THREADS) cw2[i] = g[i];
        g = P.in[31]; if (tid == 0) cb2[0] = g[0];
    }
    __syncthreads();

    // pass1: a1 = relu(emb @ actor_w1^T + b), c1 = relu(emb @ critic_w1^T + b)
    // 512 threads: ts = sample lane (8), tj = output row 0..63; each thread does
    // actor row tj and critic row tj for 4 samples per subtile.
    {
        int ts = tid & 7, tj = tid >> 3;   // tj 0..63
        for (int sub = 0; sub < 4; ++sub) {
            int sb = sub * 32;
            float acc[4][2];
            #pragma unroll
            for (int u = 0; u < 4; u++) { acc[u][0] = 0.f; acc[u][1] = 0.f; }

            #pragma unroll 4
            for (int k = 0; k < 64; k += 4) {
                float4 xv[4];
                #pragma unroll
                for (int u = 0; u < 4; u++)
                    xv[u] = *reinterpret_cast<const float4*>(&Xp[(sb + ts + 8 * u) * PX + k]);
                float4 wa = *reinterpret_cast<const float4*>(&HW[tj * PX + k]);
                float4 wc = *reinterpret_cast<const float4*>(&HW[(64 + tj) * PX + k]);
                #pragma unroll
                for (int u = 0; u < 4; u++) {
                    acc[u][0] += xv[u].x * wa.x + xv[u].y * wa.y + xv[u].z * wa.z + xv[u].w * wa.w;
                    acc[u][1] += xv[u].x * wc.x + xv[u].y * wc.y + xv[u].z * wc.z + xv[u].w * wc.w;
                }
            }
            #pragma unroll
            for (int u = 0; u < 4; u++) {
                int s = sb + ts + 8 * u;
                Hp[s * PX + tj] = fmaxf(acc[u][0] + ab1[tj], 0.f);
                C1[s * PX + tj] = fmaxf(acc[u][1] + cb1[tj], 0.f);
            }
        }
    }
    __syncthreads();

    // final: logits + log_softmax (even threads of first 256), value (odd threads)
    if (tid < 256) {
        int s2 = tid >> 1;
        int gs = gs0 + s2;
        if ((tid & 1) == 0) {
            float l0 = ab2[0], l1 = ab2[1], l2 = ab2[2];
            #pragma unroll 8
            for (int k = 0; k < 64; k++) {
                float a = Hp[s2 * PX + k];
                l0 += a * aw2[k];
                l1 += a * aw2[64 + k];
                l2 += a * aw2[128 + k];
            }
            float mx = fmaxf(l0, fmaxf(l1, l2));
            float lse = mx + logf(expf(l0 - mx) + expf(l1 - mx) + expf(l2 - mx));
            P.out[(size_t)gs * 3 + 0] = l0 - lse;
            P.out[(size_t)gs * 3 + 1] = l1 - lse;
            P.out[(size_t)gs * 3 + 2] = l2 - lse;
        } else {
            float v = cb2[0];
            #pragma unroll 8
            for (int k = 0; k < 64; k++) v += C1[s2 * PX + k] * cw2[k];
            P.out[(size_t)3 * Btot + gs] = v;
        }
    }
}

extern "C" void kernel_launch(void* const* d_in, const int* in_sizes, int n_in,
                              void* d_out, int out_size)
{
    KParams P;
    for (int i = 0; i < 32; i++) P.in[i] = (const float*)d_in[i];
    P.out = (float*)d_out;
    P.B = in_sizes[1] / 256;   // memory is [B, 256]

    cudaFuncSetAttribute(fused_gru_ac_kernel,
                         cudaFuncAttributeMaxDynamicSharedMemorySize, SMEM_BYTES);

    int grid = P.B / TB;
    fused_gru_ac_kernel<<<grid, THREADS, SMEM_BYTES>>>(P);
}